// round 13
// baseline (speedup 1.0000x reference)
#include <cuda_runtime.h>
#include <cuda_fp16.h>
#include <math_constants.h>
#include <cstdint>
#include <cstddef>

static constexpr int Vv = 16000, Cc = 4096, Hh = 256, SPW = 32, Nn = 32, Tt = 128, Tm1 = 127;

// ---------------- scratch layout ----------------
constexpr size_t SZ_MAT   = (size_t)Cc * Hh;
constexpr size_t OFF_RP   = 0;
constexpr size_t OFF_TRANS= OFF_RP   + SZ_MAT;                // 4096x4096
constexpr size_t OFF_TLSE = OFF_TRANS+ (size_t)Cc * Cc;
constexpr size_t OFF_SLOG = OFF_TLSE + Cc;
constexpr size_t OFF_SLSE = OFF_SLOG + Cc;
constexpr size_t OFF_EWT  = OFF_SLSE + 32;                    // V x H
constexpr size_t OFF_L    = OFF_EWT  + (size_t)Vv * Hh;       // V x SPW
constexpr size_t OFF_RSUM = OFF_L    + (size_t)Vv * SPW;
constexpr size_t OFF_STLSE= OFF_RSUM + Cc;
constexpr size_t OFF_PHI  = OFF_STLSE+ Cc;                    // Tm1*N*32*32
constexpr size_t OFF_AP   = OFF_PHI  + (size_t)Tm1 * Nn * SPW * SPW;
constexpr size_t OFF_BN   = OFF_AP   + (size_t)Tm1 * Nn * SPW;
constexpr size_t OFF_LOGZ = OFF_BN   + (size_t)Tm1 * Nn * SPW;
constexpr size_t OFF_PART = OFF_LOGZ + 64;                    // 4096 x 128 x (m,s)
constexpr size_t SCRATCH_TOTAL = OFF_PART + (size_t)Cc * 128 * 2;

__device__ float g_scr[SCRATCH_TOTAL];
__device__ int   g_rowmax[Cc];

// fp16 split buffers (u32 units; aliased as __half)
constexpr size_t WSZ = (size_t)Hh * Hh;
constexpr size_t HS  = SZ_MAT / 2;
constexpr size_t HWS = WSZ / 2;
constexpr size_t RSTh = 0, RSTl = HS;
constexpr size_t NSPh = 2 * HS, NSPl = 3 * HS;
constexpr size_t HEMB = 4 * HS;
constexpr size_t HOUT = 10 * HS;
constexpr size_t HWB  = 16 * HS;
__device__ uint32_t g_u[16 * HS + 12 * HWS];

// ---------------- helpers ----------------
__device__ __forceinline__ int ford(float f) {
    int i = __float_as_int(f);
    return i >= 0 ? i : (i ^ 0x7fffffff);
}
__device__ __forceinline__ float deord(int i) {
    return __int_as_float(i >= 0 ? i : (i ^ 0x7fffffff));
}
__device__ __forceinline__ void lse_acc(float& m, float& s, float v) {
    if (v > m) { s = s * __expf(m - v) + 1.f; m = v; }
    else       { s += __expf(v - m); }
}
__device__ __forceinline__ void lse_merge(float& m, float& s, float m2, float s2) {
    if (m2 > m) { s = s * __expf(m - m2) + s2; m = m2; }
    else        { s += s2 * __expf(m2 - m); }
}
__device__ __forceinline__ float warp_sum(float v) {
#pragma unroll
    for (int o = 16; o > 0; o >>= 1) v += __shfl_xor_sync(0xffffffffu, v, o);
    return v;
}
__device__ __forceinline__ float warp_max(float v) {
#pragma unroll
    for (int o = 16; o > 0; o >>= 1) v = fmaxf(v, __shfl_xor_sync(0xffffffffu, v, o));
    return v;
}

// ---------------- fp16 utils ----------------
__device__ __forceinline__ void h_split(float x, __half& hi, __half& lo) {
    hi = __float2half_rn(x);
    lo = __float2half_rn(x - __half2float(hi));
}
__device__ __forceinline__ void mma_f16(float4& d, const uint32_t* a, const uint32_t* b) {
    asm volatile(
        "mma.sync.aligned.m16n8k16.row.col.f32.f16.f16.f32 "
        "{%0,%1,%2,%3}, {%4,%5,%6,%7}, {%8,%9}, {%0,%1,%2,%3};"
        : "+f"(d.x), "+f"(d.y), "+f"(d.z), "+f"(d.w)
        : "r"(a[0]), "r"(a[1]), "r"(a[2]), "r"(a[3]), "r"(b[0]), "r"(b[1]));
}
__device__ __forceinline__ void ldsm4(uint32_t& r0, uint32_t& r1, uint32_t& r2, uint32_t& r3,
                                      uint32_t addr) {
    asm volatile("ldmatrix.sync.aligned.m8n8.x4.shared.b16 {%0,%1,%2,%3}, [%4];"
                 : "=r"(r0), "=r"(r1), "=r"(r2), "=r"(r3) : "r"(addr));
}
__device__ __forceinline__ void cpasync16(uint32_t dst, const void* src) {
    asm volatile("cp.async.cg.shared.global [%0], [%1], 16;" :: "r"(dst), "l"(src));
}
__device__ __forceinline__ void cp_commit() { asm volatile("cp.async.commit_group;"); }
template <int N> __device__ __forceinline__ void cp_wait() {
    asm volatile("cp.async.wait_group %0;" :: "n"(N));
}

// ---------------- prep kernels ----------------
struct Prep {
    const float* psrc[4]; __half* phid[4]; __half* plod[4];
    const float* wsrc[6]; __half* whid[6]; __half* wlod[6];
};
__global__ __launch_bounds__(256) void prep_k(Prep P) {
    __shared__ float t[32][33];
    int b = blockIdx.x, tid = threadIdx.x;
    if (b < 4096) {
        int mat = b >> 10;
        int i = (b & 1023) * 256 + tid;
        float4 v = ((const float4*)P.psrc[mat])[i];
        __half hx, lx, hy, ly, hz, lz, hw, lw;
        h_split(v.x, hx, lx); h_split(v.y, hy, ly);
        h_split(v.z, hz, lz); h_split(v.w, hw, lw);
        __half2 h01 = __halves2half2(hx, hy), h23 = __halves2half2(hz, hw);
        __half2 l01 = __halves2half2(lx, ly), l23 = __halves2half2(lz, lw);
        uint2 hv, lv;
        hv.x = *(uint32_t*)&h01; hv.y = *(uint32_t*)&h23;
        lv.x = *(uint32_t*)&l01; lv.y = *(uint32_t*)&l23;
        ((uint2*)P.phid[mat])[i] = hv;
        ((uint2*)P.plod[mat])[i] = lv;
    } else {
        int idx = b - 4096;
        int mat = idx >> 6, p = idx & 63;
        int bx = (p & 7) * 32, by = (p >> 3) * 32;
        int x = tid & 31, y = tid >> 5;
        const float* w = P.wsrc[mat];
#pragma unroll
        for (int i = 0; i < 32; i += 8)
            t[y + i][x] = w[(size_t)(by + y + i) * Hh + bx + x];
        __syncthreads();
#pragma unroll
        for (int i = 0; i < 32; i += 8) {
            float v = t[x][y + i];
            __half h, l;
            h_split(v, h, l);
            P.whid[mat][(size_t)(bx + y + i) * Hh + by + x] = h;
            P.wlod[mat][(size_t)(bx + y + i) * Hh + by + x] = l;
        }
    }
}

__global__ __launch_bounds__(256) void prep2_k(
    const float* __restrict__ ew, float* __restrict__ ewt,
    int* __restrict__ rm, float* __restrict__ rsum,
    float* __restrict__ slg, const float* __restrict__ soutb)
{
    __shared__ float t[32][33];
    int b = blockIdx.x, tid = threadIdx.x;
    if (b < 4000) {
        int bx = (b % 500) * 32, by = (b / 500) * 32;
        int x = tid & 31, y = tid >> 5;
#pragma unroll
        for (int i = 0; i < 32; i += 8)
            t[y + i][x] = ew[(size_t)(by + y + i) * Vv + bx + x];
        __syncthreads();
#pragma unroll
        for (int i = 0; i < 32; i += 8)
            ewt[(size_t)(bx + y + i) * Hh + by + x] = t[x][y + i];
    } else {
        int i = (b - 4000) * 256 + tid;
        if (i < Cc) { rm[i] = (int)0x80000000; rsum[i] = 0.f; }
        else        { slg[i - Cc] = soutb[0]; }
    }
}

// ---------------- MLP GEMM: fp16 3-split, ldmatrix, 128x64 tile, 4-stage -------
struct PH { const __half *Ah, *Al, *Bh, *Bl; const float *bias, *R, *sw;
            float *C; __half *Oh, *Ol; };
struct PH3 { PH p[3]; };

template <int EPI>
__global__ __launch_bounds__(256) void gemmp_h(PH3 bt, float* __restrict__ slogp, int N) {
    constexpr int NIT = 16, BUFB = 18432;
    extern __shared__ uint32_t dsm_p[];                // 4 stages = 73728 B
    const PH pp = bt.p[blockIdx.z];
    int tid = threadIdx.x, wid = tid >> 5, lane = tid & 31;
    int gid = lane >> 2, tg = lane & 3;
    int bm = blockIdx.y * 128, bn = blockIdx.x * 64;
    int warp_m = (wid & 3) * 32, warp_n = (wid >> 2) * 32;

    const __half* gsrc[3]; uint32_t doff[3];
#pragma unroll
    for (int i = 0; i < 3; i++) {
        int ch = tid + i * 256;
        if (ch < 512) {
            int mat = ch >> 8, r = (ch >> 1) & 127, c = ch & 1;
            gsrc[i] = (mat ? pp.Al : pp.Ah) + (size_t)(bm + r) * 256 + c * 8;
            doff[i] = mat * 6144 + r * 48 + c * 16;
        } else {
            int idx = ch - 512;
            int mat = idx >> 7, r = (idx >> 1) & 63, c = idx & 1;
            gsrc[i] = (mat ? pp.Bl : pp.Bh) + (size_t)(bn + r) * 256 + c * 8;
            doff[i] = 12288 + mat * 3072 + r * 48 + c * 16;
        }
    }
    uint32_t sbase = (uint32_t)__cvta_generic_to_shared(dsm_p);
    int lr = lane & 7, lg = lane >> 3;
    uint32_t a_off = (uint32_t)(((lg & 1) * 8 + lr) * 48 + (lg >> 1) * 16);
    uint32_t b_off = (uint32_t)(((lg >> 1) * 8 + lr) * 48 + (lg & 1) * 16);

    float4 acc[2][4];
#pragma unroll
    for (int i = 0; i < 2; i++)
#pragma unroll
        for (int j = 0; j < 4; j++) acc[i][j] = make_float4(0.f, 0.f, 0.f, 0.f);

#pragma unroll
    for (int s = 0; s < 3; s++) {
#pragma unroll
        for (int i = 0; i < 3; i++) cpasync16(sbase + s * BUFB + doff[i], gsrc[i] + s * 16);
        cp_commit();
    }
    for (int it = 0; it < NIT; it++) {
        cp_wait<2>();
        __syncthreads();
        uint32_t bufb = sbase + (it & 3) * BUFB;
        uint32_t ah[2][4], al[2][4], bh[4][2], bl[4][2];
#pragma unroll
        for (int mt = 0; mt < 2; mt++) {
            uint32_t ab = bufb + (uint32_t)((warp_m + mt * 16) * 48) + a_off;
            ldsm4(ah[mt][0], ah[mt][1], ah[mt][2], ah[mt][3], ab);
            ldsm4(al[mt][0], al[mt][1], al[mt][2], al[mt][3], ab + 6144);
        }
#pragma unroll
        for (int np = 0; np < 2; np++) {
            uint32_t bb = bufb + 12288u + (uint32_t)((warp_n + np * 16) * 48) + b_off;
            ldsm4(bh[2 * np][0], bh[2 * np][1], bh[2 * np + 1][0], bh[2 * np + 1][1], bb);
            ldsm4(bl[2 * np][0], bl[2 * np][1], bl[2 * np + 1][0], bl[2 * np + 1][1], bb + 3072);
        }
#pragma unroll
        for (int mt = 0; mt < 2; mt++)
#pragma unroll
            for (int nt = 0; nt < 4; nt++) {
                mma_f16(acc[mt][nt], ah[mt], bh[nt]);
                mma_f16(acc[mt][nt], al[mt], bh[nt]);
                mma_f16(acc[mt][nt], ah[mt], bl[nt]);
            }
        if (it + 3 < NIT) {
            uint32_t b = sbase + ((it + 3) & 3) * BUFB;
#pragma unroll
            for (int i = 0; i < 3; i++) cpasync16(b + doff[i], gsrc[i] + (it + 3) * 16);
        }
        cp_commit();
    }

#pragma unroll
    for (int mt = 0; mt < 2; mt++) {
        int row0 = bm + warp_m + mt * 16 + gid;
        float pr0 = 0.f, pr8 = 0.f;
#pragma unroll
        for (int nt = 0; nt < 4; nt++) {
            int col = bn + warp_n + nt * 8 + 2 * tg;
            float4 v = acc[mt][nt];
            float b0 = pp.bias[col], b1 = pp.bias[col + 1];
            v.x = fmaxf(v.x + b0, 0.f); v.y = fmaxf(v.y + b1, 0.f);
            v.z = fmaxf(v.z + b0, 0.f); v.w = fmaxf(v.w + b1, 0.f);
            if (EPI == 2) {
                float2 r0 = *(const float2*)&pp.R[(size_t)row0 * N + col];
                float2 r1 = *(const float2*)&pp.R[(size_t)(row0 + 8) * N + col];
                v.x += r0.x; v.y += r0.y; v.z += r1.x; v.w += r1.y;
                if (pp.sw) {
                    float w0 = pp.sw[col], w1 = pp.sw[col + 1];
                    pr0 += v.x * w0 + v.y * w1;
                    pr8 += v.z * w0 + v.w * w1;
                }
            }
            if (pp.C) {
                *(float2*)&pp.C[(size_t)row0 * N + col] = make_float2(v.x, v.y);
                *(float2*)&pp.C[(size_t)(row0 + 8) * N + col] = make_float2(v.z, v.w);
            }
            if (pp.Oh) {
                __half hx, lx, hy, ly, hz, lz, hw, lw;
                h_split(v.x, hx, lx); h_split(v.y, hy, ly);
                h_split(v.z, hz, lz); h_split(v.w, hw, lw);
                *(__half2*)&pp.Oh[(size_t)row0 * N + col] = __halves2half2(hx, hy);
                *(__half2*)&pp.Ol[(size_t)row0 * N + col] = __halves2half2(lx, ly);
                *(__half2*)&pp.Oh[(size_t)(row0 + 8) * N + col] = __halves2half2(hz, hw);
                *(__half2*)&pp.Ol[(size_t)(row0 + 8) * N + col] = __halves2half2(lz, lw);
            }
        }
        if (EPI == 2 && pp.sw) {
            pr0 += __shfl_xor_sync(0xffffffffu, pr0, 1);
            pr0 += __shfl_xor_sync(0xffffffffu, pr0, 2);
            pr8 += __shfl_xor_sync(0xffffffffu, pr8, 1);
            pr8 += __shfl_xor_sync(0xffffffffu, pr8, 2);
            if (tg == 0) {
                atomicAdd(&slogp[row0], pr0);
                atomicAdd(&slogp[row0 + 8], pr8);
            }
        }
    }
}

// ---------------- trans GEMM: fp16 3-split, ldmatrix, 128x128, 4-stage, 2 blocks/SM --
__global__ __launch_bounds__(256, 2) void gemm2_h(
    const __half* __restrict__ Ahg, const __half* __restrict__ Alg,
    const __half* __restrict__ Bhg, const __half* __restrict__ Blg,
    float* __restrict__ C, float2* __restrict__ part)
{
    constexpr int NIT = 16, BUFB = 24576;
    extern __shared__ uint32_t dsm_g[];                // 4 stages = 98304 B
    int tid = threadIdx.x, wid = tid >> 5, lane = tid & 31;
    int gid = lane >> 2, tg = lane & 3;
    int bm = blockIdx.y * 128, bn = blockIdx.x * 128;
    int warp_m = (wid & 1) * 64, warp_n = (wid >> 1) * 32;

    const __half* gsrc[4]; uint32_t doff[4];
#pragma unroll
    for (int i = 0; i < 4; i++) {
        int ch = tid + i * 256;
        int mat = ch >> 8;
        int idx = ch & 255, r = idx >> 1, c = idx & 1;
        const __half* g = (mat == 0) ? Ahg : (mat == 1) ? Alg : (mat == 2) ? Bhg : Blg;
        int row = ((mat < 2) ? bm : bn) + r;
        gsrc[i] = g + (size_t)row * 256 + c * 8;
        doff[i] = mat * 6144 + r * 48 + c * 16;
    }
    uint32_t sbase = (uint32_t)__cvta_generic_to_shared(dsm_g);
    int lr = lane & 7, lg = lane >> 3;
    uint32_t a_off = (uint32_t)(((lg & 1) * 8 + lr) * 48 + (lg >> 1) * 16);
    uint32_t b_off = (uint32_t)(((lg >> 1) * 8 + lr) * 48 + (lg & 1) * 16);

    float4 acc[4][4];
#pragma unroll
    for (int i = 0; i < 4; i++)
#pragma unroll
        for (int j = 0; j < 4; j++) acc[i][j] = make_float4(0.f, 0.f, 0.f, 0.f);

#pragma unroll
    for (int s = 0; s < 3; s++) {
#pragma unroll
        for (int i = 0; i < 4; i++) cpasync16(sbase + s * BUFB + doff[i], gsrc[i] + s * 16);
        cp_commit();
    }
    for (int it = 0; it < NIT; it++) {
        cp_wait<2>();
        __syncthreads();
        uint32_t bufb = sbase + (it & 3) * BUFB;
        uint32_t ah[4][4], al[4][4], bh[4][2], bl[4][2];
#pragma unroll
        for (int mt = 0; mt < 4; mt++) {
            uint32_t ab = bufb + (uint32_t)((warp_m + mt * 16) * 48) + a_off;
            ldsm4(ah[mt][0], ah[mt][1], ah[mt][2], ah[mt][3], ab);
            ldsm4(al[mt][0], al[mt][1], al[mt][2], al[mt][3], ab + 6144);
        }
#pragma unroll
        for (int np = 0; np < 2; np++) {
            uint32_t bb = bufb + 12288u + (uint32_t)((warp_n + np * 16) * 48) + b_off;
            ldsm4(bh[2 * np][0], bh[2 * np][1], bh[2 * np + 1][0], bh[2 * np + 1][1], bb);
            ldsm4(bl[2 * np][0], bl[2 * np][1], bl[2 * np + 1][0], bl[2 * np + 1][1], bb + 6144);
        }
#pragma unroll
        for (int mt = 0; mt < 4; mt++)
#pragma unroll
            for (int nt = 0; nt < 4; nt++) {
                mma_f16(acc[mt][nt], ah[mt], bh[nt]);
                mma_f16(acc[mt][nt], al[mt], bh[nt]);
                mma_f16(acc[mt][nt], ah[mt], bl[nt]);
            }
        if (it + 3 < NIT) {
            uint32_t b = sbase + ((it + 3) & 3) * BUFB;
#pragma unroll
            for (int i = 0; i < 4; i++) cpasync16(b + doff[i], gsrc[i] + (it + 3) * 16);
        }
        cp_commit();
    }

    int chunk = blockIdx.x * 4 + (wid >> 1);
#pragma unroll
    for (int mt = 0; mt < 4; mt++) {
        int row0 = bm + warp_m + mt * 16 + gid;
        float m0 = -CUDART_INF_F, s0 = 0.f, m8 = -CUDART_INF_F, s8 = 0.f;
#pragma unroll
        for (int nt = 0; nt < 4; nt++) {
            int col = bn + warp_n + nt * 8 + 2 * tg;
            float4 v = acc[mt][nt];
            *(float2*)&C[(size_t)row0 * Cc + col] = make_float2(v.x, v.y);
            *(float2*)&C[(size_t)(row0 + 8) * Cc + col] = make_float2(v.z, v.w);
            lse_acc(m0, s0, v.x); lse_acc(m0, s0, v.y);
            lse_acc(m8, s8, v.z); lse_acc(m8, s8, v.w);
        }
#pragma unroll
        for (int o = 1; o <= 2; o <<= 1) {
            float m2 = __shfl_xor_sync(0xffffffffu, m0, o);
            float s2 = __shfl_xor_sync(0xffffffffu, s0, o);
            lse_merge(m0, s0, m2, s2);
            m2 = __shfl_xor_sync(0xffffffffu, m8, o);
            s2 = __shfl_xor_sync(0xffffffffu, s8, o);
            lse_merge(m8, s8, m2, s2);
        }
        if (tg == 0) {
            part[(size_t)row0 * 128 + chunk] = make_float2(m0, s0);
            part[(size_t)(row0 + 8) * 128 + chunk] = make_float2(m8, s8);
        }
    }
}

// merge: 512 blocks, tlse rows only
__global__ void merge_k(const float2* __restrict__ part, float* __restrict__ tlse) {
    int tid = threadIdx.x;
    int row = blockIdx.x * 8 + (tid >> 5);
    int lane = tid & 31;
    float m = -CUDART_INF_F, s = 0.f;
#pragma unroll
    for (int i = 0; i < 4; i++) {
        float2 p = part[(size_t)row * 128 + lane + 32 * i];
        lse_merge(m, s, p.x, p.y);
    }
#pragma unroll
    for (int o = 16; o > 0; o >>= 1) {
        float m2 = __shfl_xor_sync(0xffffffffu, m, o);
        float s2 = __shfl_xor_sync(0xffffffffu, s, o);
        lse_merge(m, s, m2, s2);
    }
    if (lane == 0) tlse[row] = m + __logf(s);
}

// sparse emission logits
__global__ __launch_bounds__(256) void emlog_k(
    const float* __restrict__ pre, const float* __restrict__ ewT,
    const float* __restrict__ eb, const int* __restrict__ w2s,
    float* __restrict__ L, int* __restrict__ rowmax)
{
    int v = blockIdx.x;
    __shared__ float4 ecol4[64];
    __shared__ int st[SPW];
    int tid = threadIdx.x;
    if (tid < 64) ecol4[tid] = ((const float4*)(ewT + (size_t)v * Hh))[tid];
    if (tid >= 224) st[tid - 224] = w2s[v * SPW + (tid - 224)];
    __syncthreads();
    int w = tid >> 5, lane = tid & 31;
    float4 e0 = ecol4[lane], e1 = ecol4[lane + 32];
    float bv = eb[v];
#pragma unroll
    for (int q = 0; q < 4; q++) {
        int jj = w + q * 8;
        int c = st[jj];
        const float4* pr = (const float4*)(pre + (size_t)c * Hh);
        float4 p0 = pr[lane], p1 = pr[lane + 32];
        float p = p0.x * e0.x + p0.y * e0.y + p0.z * e0.z + p0.w * e0.w
                + p1.x * e1.x + p1.y * e1.y + p1.z * e1.z + p1.w * e1.w;
        p = warp_sum(p);
        if (lane == 0) {
            float val = p + bv;
            L[v * SPW + jj] = val;
            atomicMax(&rowmax[c], ford(val));
        }
    }
}

__global__ void emsum_k(const int* __restrict__ w2s, const float* __restrict__ L,
                        const int* __restrict__ rm, float* __restrict__ rsum) {
    int gid = blockIdx.x * 256 + threadIdx.x;
    int v = gid >> 5, j = gid & 31;
    int c = w2s[v * SPW + j];
    for (int jp = 0; jp < j; jp++)
        if (w2s[v * SPW + jp] == c) return;
    atomicAdd(&rsum[c], __expf(L[gid] - deord(rm[c])));
}

// blocks [0,16): stlse; block 16: slse from slog
__global__ void stlse_k(const int* __restrict__ rm, const float* __restrict__ rsum,
                        float* __restrict__ stlse, const float* __restrict__ slog,
                        float* __restrict__ slse) {
    int tid = threadIdx.x;
    if (blockIdx.x < 16) {
        int i = blockIdx.x * 256 + tid;
        stlse[i] = deord(rm[i]) + __logf(rsum[i]);
    } else {
        float m = -CUDART_INF_F, s = 0.f;
        for (int i = tid; i < Cc; i += 256) lse_acc(m, s, slog[i]);
#pragma unroll
        for (int o = 16; o > 0; o >>= 1) {
            float m2 = __shfl_xor_sync(0xffffffffu, m, o);
            float s2 = __shfl_xor_sync(0xffffffffu, s, o);
            lse_merge(m, s, m2, s2);
        }
        __shared__ float sm[8], ss[8];
        int w = tid >> 5, lane = tid & 31;
        if (lane == 0) { sm[w] = m; ss[w] = s; }
        __syncthreads();
        if (tid == 0) {
            float M = sm[0], S = ss[0];
            for (int i = 1; i < 8; i++) lse_merge(M, S, sm[i], ss[i]);
            slse[0] = M + __logf(S);
        }
    }
}

// phi with obs/init fused
__global__ __launch_bounds__(1024) void phi_k(
    const int* __restrict__ text, const int* __restrict__ w2s,
    const float* __restrict__ trans, const float* __restrict__ tlse,
    const float* __restrict__ L, const float* __restrict__ stlse,
    const float* __restrict__ slog, const float* __restrict__ slse,
    float* __restrict__ phi)
{
    int b = blockIdx.x;
    int n = b / Tm1, t = b % Tm1;
    __shared__ int c0[SPW], c1[SPW];
    __shared__ float ob1[SPW], iob[SPW], tl0[SPW];
    __shared__ float tile[SPW * 33];
    int tid = threadIdx.x;
    if (tid < SPW) {
        int v0 = text[n * Tt + t], v1 = text[n * Tt + t + 1];
        int cc0 = w2s[v0 * SPW + tid], cc1 = w2s[v1 * SPW + tid];
        c0[tid] = cc0; c1[tid] = cc1;
        tl0[tid] = tlse[cc0];
        ob1[tid] = L[v1 * SPW + tid] - stlse[cc1];
        iob[tid] = (t == 0)
            ? (slog[cc0] - slse[0] + L[v0 * SPW + tid] - stlse[cc0]) : 0.f;
    }
    __syncthreads();
    int jw = tid >> 5, kl = tid & 31;
    float val = __ldg(&trans[(size_t)c0[jw] * Cc + c1[kl]]) - tl0[jw] + ob1[kl] + iob[jw];
    tile[jw * 33 + kl] = val;
    __syncthreads();
    int kw = tid >> 5, jl = tid & 31;
    phi[(size_t)(t * Nn + n) * 1024 + kw * SPW + jl] = tile[jl * 33 + kw];
}

// forward / backward scans
__global__ __launch_bounds__(1024) void scan_k(
    const float* __restrict__ phi, float* __restrict__ ap, float* __restrict__ bn,
    float* __restrict__ logZ, float* __restrict__ out)
{
    __shared__ float a_s[2][SPW];
    int tid = threadIdx.x, w = tid >> 5, lane = tid & 31;
    bool bwd = blockIdx.x >= Nn;
    int n = bwd ? (int)blockIdx.x - Nn : (int)blockIdx.x;
    if (tid < SPW) a_s[0][tid] = 0.f;
    __syncthreads();
    int cur = 0;
    if (!bwd) {
        float pv = phi[(size_t)n * 1024 + tid];
        for (int t = 0; t < Tm1; t++) {
            float pvn = (t + 1 < Tm1) ? phi[(size_t)((t + 1) * Nn + n) * 1024 + tid] : 0.f;
            if (tid < SPW) ap[(size_t)(t * Nn + n) * SPW + tid] = a_s[cur][tid];
            float x = pv + a_s[cur][lane];
            float m = warp_max(x);
            float s = warp_sum(__expf(x - m));
            if (lane == 0) a_s[cur ^ 1][w] = m + __logf(s);
            __syncthreads();
            cur ^= 1;
            pv = pvn;
        }
        if (w == 0) {
            float x = a_s[cur][lane];
            float m = warp_max(x);
            float s = warp_sum(__expf(x - m));
            float lz = m + __logf(s);
            if (lane == 0) logZ[n] = lz;
            out[2 + n * SPW + lane] = x - lz;
        }
        if (n == 0 && tid == 1023) out[0] = 0.f;
    } else {
        float pv = phi[(size_t)((Tm1 - 1) * Nn + n) * 1024 + lane * SPW + w];
        for (int t = Tm1 - 1; t >= 0; t--) {
            float pvn = (t > 0) ? phi[(size_t)((t - 1) * Nn + n) * 1024 + lane * SPW + w] : 0.f;
            if (tid < SPW) bn[(size_t)(t * Nn + n) * SPW + tid] = a_s[cur][tid];
            float x = pv + a_s[cur][lane];
            float m = warp_max(x);
            float s = warp_sum(__expf(x - m));
            if (lane == 0) a_s[cur ^ 1][w] = m + __logf(s);
            __syncthreads();
            cur ^= 1;
            pv = pvn;
        }
    }
}

// elbo + evidence fused
__global__ __launch_bounds__(1024) void elbo_k(
    const float* __restrict__ phi, const float* __restrict__ ap,
    const float* __restrict__ bn, const float* __restrict__ logZ,
    float* __restrict__ out)
{
    int e = blockIdx.x;
    int n = e % Nn;
    __shared__ float sap[SPW], sbn[SPW], ws[32];
    int tid = threadIdx.x;
    if (tid < SPW) { sap[tid] = ap[(size_t)e * SPW + tid]; sbn[tid] = bn[(size_t)e * SPW + tid]; }
    __syncthreads();
    int k = tid >> 5, j = tid & 31;
    float p = phi[(size_t)e * 1024 + tid];
    float term = __expf(sap[j] + p + sbn[k] - logZ[n]) * p;
    term = warp_sum(term);
    if (j == 0) ws[k] = term;
    __syncthreads();
    if (tid < 32) {
        float v = warp_sum(ws[tid]);
        if (tid == 0) atomicAdd(&out[0], v);
    }
    if (e == 0 && tid >= 64 && tid < 96) {
        int lane2 = tid - 64;
        float lz = logZ[lane2];
        lz = warp_sum(lz);
        if (lane2 == 0) out[1] = lz;
    }
}

// ---------------- launcher ----------------
extern "C" void kernel_launch(void* const* d_in, const int* in_sizes, int n_in,
                              void* d_out, int out_size) {
    const float* start_emb = (const float*)d_in[0];
    const float* sw1  = (const float*)d_in[1];
    const float* sb1  = (const float*)d_in[2];
    const float* sw2  = (const float*)d_in[3];
    const float* sb2  = (const float*)d_in[4];
    const float* s_out_w = (const float*)d_in[5];
    const float* s_out_b = (const float*)d_in[6];
    const float* state_emb = (const float*)d_in[7];
    const float* tw1  = (const float*)d_in[8];
    const float* tb1  = (const float*)d_in[9];
    const float* tw2  = (const float*)d_in[10];
    const float* tb2  = (const float*)d_in[11];
    const float* nsp  = (const float*)d_in[12];
    const float* pre_emb = (const float*)d_in[13];
    const float* ew1  = (const float*)d_in[14];
    const float* eb1  = (const float*)d_in[15];
    const float* ew2  = (const float*)d_in[16];
    const float* eb2  = (const float*)d_in[17];
    const float* e_out_w = (const float*)d_in[18];
    const float* e_out_b = (const float*)d_in[19];
    const int* text = (const int*)d_in[20];
    const int* w2s  = (const int*)d_in[21];
    float* out = (float*)d_out;

    float* S = nullptr; int* RM = nullptr; uint32_t* U = nullptr;
    cudaGetSymbolAddress((void**)&S, g_scr);
    cudaGetSymbolAddress((void**)&RM, g_rowmax);
    cudaGetSymbolAddress((void**)&U, g_u);

    static bool inited = false;
    static cudaStream_t s1;
    static cudaEvent_t evStart, evB2, evEm;
    if (!inited) {
        cudaStreamCreateWithFlags(&s1, cudaStreamNonBlocking);
        cudaEventCreateWithFlags(&evStart, cudaEventDisableTiming);
        cudaEventCreateWithFlags(&evB2, cudaEventDisableTiming);
        cudaEventCreateWithFlags(&evEm, cudaEventDisableTiming);
        cudaFuncSetAttribute(gemm2_h, cudaFuncAttributeMaxDynamicSharedMemorySize, 98304);
        cudaFuncSetAttribute(gemmp_h<1>, cudaFuncAttributeMaxDynamicSharedMemorySize, 73728);
        cudaFuncSetAttribute(gemmp_h<2>, cudaFuncAttributeMaxDynamicSharedMemorySize, 73728);
        inited = true;
    }

    auto HW = [&](int j) { return (__half*)(U + HWB + (size_t)j * 2 * HWS); };
    auto HWl = [&](int j) { return (__half*)(U + HWB + (size_t)j * 2 * HWS + HWS); };
    auto HE = [&](int j) { return (__half*)(U + HEMB + (size_t)j * 2 * HS); };
    auto HEl = [&](int j) { return (__half*)(U + HEMB + (size_t)j * 2 * HS + HS); };
    auto HO = [&](int j) { return (__half*)(U + HOUT + (size_t)j * 2 * HS); };
    auto HOl = [&](int j) { return (__half*)(U + HOUT + (size_t)j * 2 * HS + HS); };

    cudaEventRecord(evStart, 0);
    cudaStreamWaitEvent(s1, evStart, 0);

    // ---- s1: ewT transpose + inits ----
    prep2_k<<<4032, 256, 0, s1>>>(e_out_w, S + OFF_EWT, RM, S + OFF_RSUM,
                                  S + OFF_SLOG, s_out_b);

    // ---- main: presplit + weight splits ----
    Prep P;
    const float* em_[4] = { start_emb, state_emb, pre_emb, nsp };
    for (int j = 0; j < 3; j++) {
        P.psrc[j] = em_[j];
        P.phid[j] = HE(j);
        P.plod[j] = HEl(j);
    }
    P.psrc[3] = nsp;
    P.phid[3] = (__half*)(U + NSPh);
    P.plod[3] = (__half*)(U + NSPl);
    const float* ws_[6] = { sw1, tw1, ew1, sw2, tw2, ew2 };
    for (int j = 0; j < 6; j++) {
        P.wsrc[j] = ws_[j];
        P.whid[j] = HW(j);
        P.wlod[j] = HWl(j);
    }
    prep_k<<<4480, 256>>>(P);

    // ---- MLPs (fp16 3-split, ldmatrix, 4-stage) ----
    const float* b1_[3] = { sb1, tb1, eb1 };
    PH3 m1;
    for (int j = 0; j < 3; j++)
        m1.p[j] = { HE(j), HEl(j), HW(j), HWl(j), b1_[j], nullptr, nullptr,
                    nullptr, HO(j), HOl(j) };
    gemmp_h<1><<<dim3(4, 32, 3), 256, 73728>>>(m1, nullptr, Hh);

    PH3 m2;
    m2.p[0] = { HO(0), HOl(0), HW(3), HWl(3), sb2, start_emb, s_out_w,
                nullptr, nullptr, nullptr };
    m2.p[1] = { HO(1), HOl(1), HW(4), HWl(4), tb2, state_emb, nullptr,
                nullptr, (__half*)(U + RSTh), (__half*)(U + RSTl) };
    m2.p[2] = { HO(2), HOl(2), HW(5), HWl(5), eb2, pre_emb, nullptr,
                S + OFF_RP, nullptr, nullptr };
    gemmp_h<2><<<dim3(4, 32, 3), 256, 73728>>>(m2, S + OFF_SLOG, Hh);
    cudaEventRecord(evB2, 0);

    // ---- s1: emission chain (concurrent with trans GEMM) ----
    cudaStreamWaitEvent(s1, evB2, 0);
    emlog_k<<<Vv, 256, 0, s1>>>(S + OFF_RP, S + OFF_EWT, e_out_b, w2s, S + OFF_L, RM);
    emsum_k<<<Vv * SPW / 256, 256, 0, s1>>>(w2s, S + OFF_L, RM, S + OFF_RSUM);
    stlse_k<<<17, 256, 0, s1>>>(RM, S + OFF_RSUM, S + OFF_STLSE, S + OFF_SLOG, S + OFF_SLSE);
    cudaEventRecord(evEm, s1);

    // ---- main: fp16 trans GEMM (4-stage, 2 blocks/SM) + tlse merge ----
    gemm2_h<<<dim3(Cc / 128, Cc / 128), 256, 98304>>>(
        (const __half*)(U + RSTh), (const __half*)(U + RSTl),
        (const __half*)(U + NSPh), (const __half*)(U + NSPl),
        S + OFF_TRANS, (float2*)(S + OFF_PART));
    merge_k<<<512, 256>>>((float2*)(S + OFF_PART), S + OFF_TLSE);

    // ---- join + tail ----
    cudaStreamWaitEvent(0, evEm, 0);
    phi_k<<<Nn * Tm1, 1024>>>(text, w2s, S + OFF_TRANS, S + OFF_TLSE,
                              S + OFF_L, S + OFF_STLSE, S + OFF_SLOG, S + OFF_SLSE,
                              S + OFF_PHI);
    scan_k<<<2 * Nn, 1024>>>(S + OFF_PHI, S + OFF_AP, S + OFF_BN, S + OFF_LOGZ, out);
    elbo_k<<<Tm1 * Nn, 1024>>>(S + OFF_PHI, S + OFF_AP, S + OFF_BN, S + OFF_LOGZ, out);
}

// round 14
// speedup vs baseline: 1.1352x; 1.1352x over previous
#include <cuda_runtime.h>
#include <cuda_fp16.h>
#include <math_constants.h>
#include <cstdint>
#include <cstddef>

static constexpr int Vv = 16000, Cc = 4096, Hh = 256, SPW = 32, Nn = 32, Tt = 128, Tm1 = 127;

// ---------------- scratch layout ----------------
constexpr size_t SZ_MAT   = (size_t)Cc * Hh;
constexpr size_t OFF_RP   = 0;
constexpr size_t OFF_TRANS= OFF_RP   + SZ_MAT;                // 4096x4096
constexpr size_t OFF_TLSE = OFF_TRANS+ (size_t)Cc * Cc;
constexpr size_t OFF_SLOG = OFF_TLSE + Cc;
constexpr size_t OFF_SLSE = OFF_SLOG + Cc;
constexpr size_t OFF_EWT  = OFF_SLSE + 32;                    // V x H
constexpr size_t OFF_L    = OFF_EWT  + (size_t)Vv * Hh;       // V x SPW
constexpr size_t OFF_RSUM = OFF_L    + (size_t)Vv * SPW;
constexpr size_t OFF_STLSE= OFF_RSUM + Cc;
constexpr size_t OFF_PHI  = OFF_STLSE+ Cc;                    // Tm1*N*32*32
constexpr size_t OFF_AP   = OFF_PHI  + (size_t)Tm1 * Nn * SPW * SPW;
constexpr size_t OFF_BN   = OFF_AP   + (size_t)Tm1 * Nn * SPW;
constexpr size_t OFF_LOGZ = OFF_BN   + (size_t)Tm1 * Nn * SPW;
constexpr size_t OFF_PART = OFF_LOGZ + 64;                    // 4096 x 128 x (m,s)
constexpr size_t SCRATCH_TOTAL = OFF_PART + (size_t)Cc * 128 * 2;

__device__ float g_scr[SCRATCH_TOTAL];
__device__ int   g_rowmax[Cc];

// fp16 split buffers (u32 units; aliased as __half)
constexpr size_t WSZ = (size_t)Hh * Hh;
constexpr size_t HS  = SZ_MAT / 2;
constexpr size_t HWS = WSZ / 2;
constexpr size_t RSTh = 0, RSTl = HS;
constexpr size_t NSPh = 2 * HS, NSPl = 3 * HS;
constexpr size_t HEMB = 4 * HS;
constexpr size_t HOUT = 10 * HS;
constexpr size_t HWB  = 16 * HS;
__device__ uint32_t g_u[16 * HS + 12 * HWS];

// ---------------- helpers ----------------
__device__ __forceinline__ int ford(float f) {
    int i = __float_as_int(f);
    return i >= 0 ? i : (i ^ 0x7fffffff);
}
__device__ __forceinline__ float deord(int i) {
    return __int_as_float(i >= 0 ? i : (i ^ 0x7fffffff));
}
__device__ __forceinline__ void lse_acc(float& m, float& s, float v) {
    if (v > m) { s = s * __expf(m - v) + 1.f; m = v; }
    else       { s += __expf(v - m); }
}
__device__ __forceinline__ void lse_merge(float& m, float& s, float m2, float s2) {
    if (m2 > m) { s = s * __expf(m - m2) + s2; m = m2; }
    else        { s += s2 * __expf(m2 - m); }
}
__device__ __forceinline__ float warp_sum(float v) {
#pragma unroll
    for (int o = 16; o > 0; o >>= 1) v += __shfl_xor_sync(0xffffffffu, v, o);
    return v;
}
__device__ __forceinline__ float warp_max(float v) {
#pragma unroll
    for (int o = 16; o > 0; o >>= 1) v = fmaxf(v, __shfl_xor_sync(0xffffffffu, v, o));
    return v;
}

// ---------------- fp16 utils ----------------
__device__ __forceinline__ void h_split(float x, __half& hi, __half& lo) {
    hi = __float2half_rn(x);
    lo = __float2half_rn(x - __half2float(hi));
}
__device__ __forceinline__ void split_store(float4 v, __half* hp, __half* lp, size_t i) {
    __half hx, lx, hy, ly, hz, lz, hw, lw;
    h_split(v.x, hx, lx); h_split(v.y, hy, ly);
    h_split(v.z, hz, lz); h_split(v.w, hw, lw);
    __half2 h01 = __halves2half2(hx, hy), h23 = __halves2half2(hz, hw);
    __half2 l01 = __halves2half2(lx, ly), l23 = __halves2half2(lz, lw);
    uint2 hv, lv;
    hv.x = *(uint32_t*)&h01; hv.y = *(uint32_t*)&h23;
    lv.x = *(uint32_t*)&l01; lv.y = *(uint32_t*)&l23;
    ((uint2*)hp)[i] = hv;
    ((uint2*)lp)[i] = lv;
}
__device__ __forceinline__ void mma_f16(float4& d, const uint32_t* a, const uint32_t* b) {
    asm volatile(
        "mma.sync.aligned.m16n8k16.row.col.f32.f16.f16.f32 "
        "{%0,%1,%2,%3}, {%4,%5,%6,%7}, {%8,%9}, {%0,%1,%2,%3};"
        : "+f"(d.x), "+f"(d.y), "+f"(d.z), "+f"(d.w)
        : "r"(a[0]), "r"(a[1]), "r"(a[2]), "r"(a[3]), "r"(b[0]), "r"(b[1]));
}
__device__ __forceinline__ void ldsm4(uint32_t& r0, uint32_t& r1, uint32_t& r2, uint32_t& r3,
                                      uint32_t addr) {
    asm volatile("ldmatrix.sync.aligned.m8n8.x4.shared.b16 {%0,%1,%2,%3}, [%4];"
                 : "=r"(r0), "=r"(r1), "=r"(r2), "=r"(r3) : "r"(addr));
}
__device__ __forceinline__ void cpasync16(uint32_t dst, const void* src) {
    asm volatile("cp.async.cg.shared.global [%0], [%1], 16;" :: "r"(dst), "l"(src));
}
__device__ __forceinline__ void cp_commit() { asm volatile("cp.async.commit_group;"); }
template <int N> __device__ __forceinline__ void cp_wait() {
    asm volatile("cp.async.wait_group %0;" :: "n"(N));
}

// ---------------- prep kernels ----------------
// prep_k (main): [0,768) presplit 3 embeddings x4 ILP; [768,1152) wt transpose+split x6.
struct Prep {
    const float* psrc[3]; __half* phid[3]; __half* plod[3];
    const float* wsrc[6]; __half* whid[6]; __half* wlod[6];
};
__global__ __launch_bounds__(256) void prep_k(Prep P) {
    __shared__ float t[32][33];
    int b = blockIdx.x, tid = threadIdx.x;
    if (b < 768) {
        int mat = b >> 8;
        size_t i0 = (size_t)(b & 255) * 1024 + tid;
        const float4* src = (const float4*)P.psrc[mat];
        float4 v0 = src[i0], v1 = src[i0 + 256], v2 = src[i0 + 512], v3 = src[i0 + 768];
        split_store(v0, P.phid[mat], P.plod[mat], i0);
        split_store(v1, P.phid[mat], P.plod[mat], i0 + 256);
        split_store(v2, P.phid[mat], P.plod[mat], i0 + 512);
        split_store(v3, P.phid[mat], P.plod[mat], i0 + 768);
    } else {
        int idx = b - 768;
        int mat = idx >> 6, p = idx & 63;
        int bx = (p & 7) * 32, by = (p >> 3) * 32;
        int x = tid & 31, y = tid >> 5;
        const float* w = P.wsrc[mat];
#pragma unroll
        for (int i = 0; i < 32; i += 8)
            t[y + i][x] = w[(size_t)(by + y + i) * Hh + bx + x];
        __syncthreads();
#pragma unroll
        for (int i = 0; i < 32; i += 8) {
            float v = t[x][y + i];
            __half h, l;
            h_split(v, h, l);
            P.whid[mat][(size_t)(bx + y + i) * Hh + by + x] = h;
            P.wlod[mat][(size_t)(bx + y + i) * Hh + by + x] = l;
        }
    }
}

// prep2_k (s1): [0,256) nsp presplit x4; [256,4256) ewT transpose; [4256,4288) inits.
__global__ __launch_bounds__(256) void prep2_k(
    const float* __restrict__ nsp, __half* __restrict__ nh, __half* __restrict__ nl,
    const float* __restrict__ ew, float* __restrict__ ewt,
    int* __restrict__ rm, float* __restrict__ rsum,
    float* __restrict__ slg, const float* __restrict__ soutb)
{
    __shared__ float t[32][33];
    int b = blockIdx.x, tid = threadIdx.x;
    if (b < 256) {
        size_t i0 = (size_t)b * 1024 + tid;
        const float4* src = (const float4*)nsp;
        float4 v0 = src[i0], v1 = src[i0 + 256], v2 = src[i0 + 512], v3 = src[i0 + 768];
        split_store(v0, nh, nl, i0);
        split_store(v1, nh, nl, i0 + 256);
        split_store(v2, nh, nl, i0 + 512);
        split_store(v3, nh, nl, i0 + 768);
    } else if (b < 4256) {
        int p = b - 256;
        int bx = (p % 500) * 32, by = (p / 500) * 32;
        int x = tid & 31, y = tid >> 5;
#pragma unroll
        for (int i = 0; i < 32; i += 8)
            t[y + i][x] = ew[(size_t)(by + y + i) * Vv + bx + x];
        __syncthreads();
#pragma unroll
        for (int i = 0; i < 32; i += 8)
            ewt[(size_t)(bx + y + i) * Hh + by + x] = t[x][y + i];
    } else {
        int i = (b - 4256) * 256 + tid;
        if (i < Cc) { rm[i] = (int)0x80000000; rsum[i] = 0.f; }
        else        { slg[i - Cc] = soutb[0]; }
    }
}

// ---------------- MLP GEMM: fp16 3-split, ldmatrix, 128x64 tile, 4-stage -------
struct PH { const __half *Ah, *Al, *Bh, *Bl; const float *bias, *R, *sw;
            float *C; __half *Oh, *Ol; };
struct PH3 { PH p[3]; };

template <int EPI>
__global__ __launch_bounds__(256) void gemmp_h(PH3 bt, float* __restrict__ slogp, int N) {
    constexpr int NIT = 16, BUFB = 18432;
    extern __shared__ uint32_t dsm_p[];
    const PH pp = bt.p[blockIdx.z];
    int tid = threadIdx.x, wid = tid >> 5, lane = tid & 31;
    int gid = lane >> 2, tg = lane & 3;
    int bm = blockIdx.y * 128, bn = blockIdx.x * 64;
    int warp_m = (wid & 3) * 32, warp_n = (wid >> 2) * 32;

    const __half* gsrc[3]; uint32_t doff[3];
#pragma unroll
    for (int i = 0; i < 3; i++) {
        int ch = tid + i * 256;
        if (ch < 512) {
            int mat = ch >> 8, r = (ch >> 1) & 127, c = ch & 1;
            gsrc[i] = (mat ? pp.Al : pp.Ah) + (size_t)(bm + r) * 256 + c * 8;
            doff[i] = mat * 6144 + r * 48 + c * 16;
        } else {
            int idx = ch - 512;
            int mat = idx >> 7, r = (idx >> 1) & 63, c = idx & 1;
            gsrc[i] = (mat ? pp.Bl : pp.Bh) + (size_t)(bn + r) * 256 + c * 8;
            doff[i] = 12288 + mat * 3072 + r * 48 + c * 16;
        }
    }
    uint32_t sbase = (uint32_t)__cvta_generic_to_shared(dsm_p);
    int lr = lane & 7, lg = lane >> 3;
    uint32_t a_off = (uint32_t)(((lg & 1) * 8 + lr) * 48 + (lg >> 1) * 16);
    uint32_t b_off = (uint32_t)(((lg >> 1) * 8 + lr) * 48 + (lg & 1) * 16);

    float4 acc[2][4];
#pragma unroll
    for (int i = 0; i < 2; i++)
#pragma unroll
        for (int j = 0; j < 4; j++) acc[i][j] = make_float4(0.f, 0.f, 0.f, 0.f);

#pragma unroll
    for (int s = 0; s < 3; s++) {
#pragma unroll
        for (int i = 0; i < 3; i++) cpasync16(sbase + s * BUFB + doff[i], gsrc[i] + s * 16);
        cp_commit();
    }
    for (int it = 0; it < NIT; it++) {
        cp_wait<2>();
        __syncthreads();
        uint32_t bufb = sbase + (it & 3) * BUFB;
        uint32_t ah[2][4], al[2][4], bh[4][2], bl[4][2];
#pragma unroll
        for (int mt = 0; mt < 2; mt++) {
            uint32_t ab = bufb + (uint32_t)((warp_m + mt * 16) * 48) + a_off;
            ldsm4(ah[mt][0], ah[mt][1], ah[mt][2], ah[mt][3], ab);
            ldsm4(al[mt][0], al[mt][1], al[mt][2], al[mt][3], ab + 6144);
        }
#pragma unroll
        for (int np = 0; np < 2; np++) {
            uint32_t bb = bufb + 12288u + (uint32_t)((warp_n + np * 16) * 48) + b_off;
            ldsm4(bh[2 * np][0], bh[2 * np][1], bh[2 * np + 1][0], bh[2 * np + 1][1], bb);
            ldsm4(bl[2 * np][0], bl[2 * np][1], bl[2 * np + 1][0], bl[2 * np + 1][1], bb + 3072);
        }
#pragma unroll
        for (int mt = 0; mt < 2; mt++)
#pragma unroll
            for (int nt = 0; nt < 4; nt++) {
                mma_f16(acc[mt][nt], ah[mt], bh[nt]);
                mma_f16(acc[mt][nt], al[mt], bh[nt]);
                mma_f16(acc[mt][nt], ah[mt], bl[nt]);
            }
        if (it + 3 < NIT) {
            uint32_t b = sbase + ((it + 3) & 3) * BUFB;
#pragma unroll
            for (int i = 0; i < 3; i++) cpasync16(b + doff[i], gsrc[i] + (it + 3) * 16);
        }
        cp_commit();
    }

#pragma unroll
    for (int mt = 0; mt < 2; mt++) {
        int row0 = bm + warp_m + mt * 16 + gid;
        float pr0 = 0.f, pr8 = 0.f;
#pragma unroll
        for (int nt = 0; nt < 4; nt++) {
            int col = bn + warp_n + nt * 8 + 2 * tg;
            float4 v = acc[mt][nt];
            float b0 = pp.bias[col], b1 = pp.bias[col + 1];
            v.x = fmaxf(v.x + b0, 0.f); v.y = fmaxf(v.y + b1, 0.f);
            v.z = fmaxf(v.z + b0, 0.f); v.w = fmaxf(v.w + b1, 0.f);
            if (EPI == 2) {
                float2 r0 = *(const float2*)&pp.R[(size_t)row0 * N + col];
                float2 r1 = *(const float2*)&pp.R[(size_t)(row0 + 8) * N + col];
                v.x += r0.x; v.y += r0.y; v.z += r1.x; v.w += r1.y;
                if (pp.sw) {
                    float w0 = pp.sw[col], w1 = pp.sw[col + 1];
                    pr0 += v.x * w0 + v.y * w1;
                    pr8 += v.z * w0 + v.w * w1;
                }
            }
            if (pp.C) {
                *(float2*)&pp.C[(size_t)row0 * N + col] = make_float2(v.x, v.y);
                *(float2*)&pp.C[(size_t)(row0 + 8) * N + col] = make_float2(v.z, v.w);
            }
            if (pp.Oh) {
                __half hx, lx, hy, ly, hz, lz, hw, lw;
                h_split(v.x, hx, lx); h_split(v.y, hy, ly);
                h_split(v.z, hz, lz); h_split(v.w, hw, lw);
                *(__half2*)&pp.Oh[(size_t)row0 * N + col] = __halves2half2(hx, hy);
                *(__half2*)&pp.Ol[(size_t)row0 * N + col] = __halves2half2(lx, ly);
                *(__half2*)&pp.Oh[(size_t)(row0 + 8) * N + col] = __halves2half2(hz, hw);
                *(__half2*)&pp.Ol[(size_t)(row0 + 8) * N + col] = __halves2half2(lz, lw);
            }
        }
        if (EPI == 2 && pp.sw) {
            pr0 += __shfl_xor_sync(0xffffffffu, pr0, 1);
            pr0 += __shfl_xor_sync(0xffffffffu, pr0, 2);
            pr8 += __shfl_xor_sync(0xffffffffu, pr8, 1);
            pr8 += __shfl_xor_sync(0xffffffffu, pr8, 2);
            if (tg == 0) {
                atomicAdd(&slogp[row0], pr0);
                atomicAdd(&slogp[row0 + 8], pr8);
            }
        }
    }
}

// ---------------- trans GEMM: fp16 3-split, ldmatrix, 128x128, 4-stage, 2 blocks/SM --
__global__ __launch_bounds__(256, 2) void gemm2_h(
    const __half* __restrict__ Ahg, const __half* __restrict__ Alg,
    const __half* __restrict__ Bhg, const __half* __restrict__ Blg,
    float* __restrict__ C, float2* __restrict__ part)
{
    constexpr int NIT = 16, BUFB = 24576;
    extern __shared__ uint32_t dsm_g[];
    int tid = threadIdx.x, wid = tid >> 5, lane = tid & 31;
    int gid = lane >> 2, tg = lane & 3;
    int bm = blockIdx.y * 128, bn = blockIdx.x * 128;
    int warp_m = (wid & 1) * 64, warp_n = (wid >> 1) * 32;

    const __half* gsrc[4]; uint32_t doff[4];
#pragma unroll
    for (int i = 0; i < 4; i++) {
        int ch = tid + i * 256;
        int mat = ch >> 8;
        int idx = ch & 255, r = idx >> 1, c = idx & 1;
        const __half* g = (mat == 0) ? Ahg : (mat == 1) ? Alg : (mat == 2) ? Bhg : Blg;
        int row = ((mat < 2) ? bm : bn) + r;
        gsrc[i] = g + (size_t)row * 256 + c * 8;
        doff[i] = mat * 6144 + r * 48 + c * 16;
    }
    uint32_t sbase = (uint32_t)__cvta_generic_to_shared(dsm_g);
    int lr = lane & 7, lg = lane >> 3;
    uint32_t a_off = (uint32_t)(((lg & 1) * 8 + lr) * 48 + (lg >> 1) * 16);
    uint32_t b_off = (uint32_t)(((lg >> 1) * 8 + lr) * 48 + (lg & 1) * 16);

    float4 acc[4][4];
#pragma unroll
    for (int i = 0; i < 4; i++)
#pragma unroll
        for (int j = 0; j < 4; j++) acc[i][j] = make_float4(0.f, 0.f, 0.f, 0.f);

#pragma unroll
    for (int s = 0; s < 3; s++) {
#pragma unroll
        for (int i = 0; i < 4; i++) cpasync16(sbase + s * BUFB + doff[i], gsrc[i] + s * 16);
        cp_commit();
    }
    for (int it = 0; it < NIT; it++) {
        cp_wait<2>();
        __syncthreads();
        uint32_t bufb = sbase + (it & 3) * BUFB;
        uint32_t ah[4][4], al[4][4], bh[4][2], bl[4][2];
#pragma unroll
        for (int mt = 0; mt < 4; mt++) {
            uint32_t ab = bufb + (uint32_t)((warp_m + mt * 16) * 48) + a_off;
            ldsm4(ah[mt][0], ah[mt][1], ah[mt][2], ah[mt][3], ab);
            ldsm4(al[mt][0], al[mt][1], al[mt][2], al[mt][3], ab + 6144);
        }
#pragma unroll
        for (int np = 0; np < 2; np++) {
            uint32_t bb = bufb + 12288u + (uint32_t)((warp_n + np * 16) * 48) + b_off;
            ldsm4(bh[2 * np][0], bh[2 * np][1], bh[2 * np + 1][0], bh[2 * np + 1][1], bb);
            ldsm4(bl[2 * np][0], bl[2 * np][1], bl[2 * np + 1][0], bl[2 * np + 1][1], bb + 6144);
        }
#pragma unroll
        for (int mt = 0; mt < 4; mt++)
#pragma unroll
            for (int nt = 0; nt < 4; nt++) {
                mma_f16(acc[mt][nt], ah[mt], bh[nt]);
                mma_f16(acc[mt][nt], al[mt], bh[nt]);
                mma_f16(acc[mt][nt], ah[mt], bl[nt]);
            }
        if (it + 3 < NIT) {
            uint32_t b = sbase + ((it + 3) & 3) * BUFB;
#pragma unroll
            for (int i = 0; i < 4; i++) cpasync16(b + doff[i], gsrc[i] + (it + 3) * 16);
        }
        cp_commit();
    }

    int chunk = blockIdx.x * 4 + (wid >> 1);
#pragma unroll
    for (int mt = 0; mt < 4; mt++) {
        int row0 = bm + warp_m + mt * 16 + gid;
        float m0 = -CUDART_INF_F, s0 = 0.f, m8 = -CUDART_INF_F, s8 = 0.f;
#pragma unroll
        for (int nt = 0; nt < 4; nt++) {
            int col = bn + warp_n + nt * 8 + 2 * tg;
            float4 v = acc[mt][nt];
            *(float2*)&C[(size_t)row0 * Cc + col] = make_float2(v.x, v.y);
            *(float2*)&C[(size_t)(row0 + 8) * Cc + col] = make_float2(v.z, v.w);
            lse_acc(m0, s0, v.x); lse_acc(m0, s0, v.y);
            lse_acc(m8, s8, v.z); lse_acc(m8, s8, v.w);
        }
#pragma unroll
        for (int o = 1; o <= 2; o <<= 1) {
            float m2 = __shfl_xor_sync(0xffffffffu, m0, o);
            float s2 = __shfl_xor_sync(0xffffffffu, s0, o);
            lse_merge(m0, s0, m2, s2);
            m2 = __shfl_xor_sync(0xffffffffu, m8, o);
            s2 = __shfl_xor_sync(0xffffffffu, s8, o);
            lse_merge(m8, s8, m2, s2);
        }
        if (tg == 0) {
            part[(size_t)row0 * 128 + chunk] = make_float2(m0, s0);
            part[(size_t)(row0 + 8) * 128 + chunk] = make_float2(m8, s8);
        }
    }
}

// merge: 512 blocks, tlse rows only
__global__ void merge_k(const float2* __restrict__ part, float* __restrict__ tlse) {
    int tid = threadIdx.x;
    int row = blockIdx.x * 8 + (tid >> 5);
    int lane = tid & 31;
    float m = -CUDART_INF_F, s = 0.f;
#pragma unroll
    for (int i = 0; i < 4; i++) {
        float2 p = part[(size_t)row * 128 + lane + 32 * i];
        lse_merge(m, s, p.x, p.y);
    }
#pragma unroll
    for (int o = 16; o > 0; o >>= 1) {
        float m2 = __shfl_xor_sync(0xffffffffu, m, o);
        float s2 = __shfl_xor_sync(0xffffffffu, s, o);
        lse_merge(m, s, m2, s2);
    }
    if (lane == 0) tlse[row] = m + __logf(s);
}

// sparse emission logits
__global__ __launch_bounds__(256) void emlog_k(
    const float* __restrict__ pre, const float* __restrict__ ewT,
    const float* __restrict__ eb, const int* __restrict__ w2s,
    float* __restrict__ L, int* __restrict__ rowmax)
{
    int v = blockIdx.x;
    __shared__ float4 ecol4[64];
    __shared__ int st[SPW];
    int tid = threadIdx.x;
    if (tid < 64) ecol4[tid] = ((const float4*)(ewT + (size_t)v * Hh))[tid];
    if (tid >= 224) st[tid - 224] = w2s[v * SPW + (tid - 224)];
    __syncthreads();
    int w = tid >> 5, lane = tid & 31;
    float4 e0 = ecol4[lane], e1 = ecol4[lane + 32];
    float bv = eb[v];
#pragma unroll
    for (int q = 0; q < 4; q++) {
        int jj = w + q * 8;
        int c = st[jj];
        const float4* pr = (const float4*)(pre + (size_t)c * Hh);
        float4 p0 = pr[lane], p1 = pr[lane + 32];
        float p = p0.x * e0.x + p0.y * e0.y + p0.z * e0.z + p0.w * e0.w
                + p1.x * e1.x + p1.y * e1.y + p1.z * e1.z + p1.w * e1.w;
        p = warp_sum(p);
        if (lane == 0) {
            float val = p + bv;
            L[v * SPW + jj] = val;
            atomicMax(&rowmax[c], ford(val));
        }
    }
}

__global__ void emsum_k(const int* __restrict__ w2s, const float* __restrict__ L,
                        const int* __restrict__ rm, float* __restrict__ rsum) {
    int gid = blockIdx.x * 256 + threadIdx.x;
    int v = gid >> 5, j = gid & 31;
    int c = w2s[v * SPW + j];
    for (int jp = 0; jp < j; jp++)
        if (w2s[v * SPW + jp] == c) return;
    atomicAdd(&rsum[c], __expf(L[gid] - deord(rm[c])));
}

// blocks [0,16): stlse; block 16: slse from slog
__global__ void stlse_k(const int* __restrict__ rm, const float* __restrict__ rsum,
                        float* __restrict__ stlse, const float* __restrict__ slog,
                        float* __restrict__ slse) {
    int tid = threadIdx.x;
    if (blockIdx.x < 16) {
        int i = blockIdx.x * 256 + tid;
        stlse[i] = deord(rm[i]) + __logf(rsum[i]);
    } else {
        float m = -CUDART_INF_F, s = 0.f;
        for (int i = tid; i < Cc; i += 256) lse_acc(m, s, slog[i]);
#pragma unroll
        for (int o = 16; o > 0; o >>= 1) {
            float m2 = __shfl_xor_sync(0xffffffffu, m, o);
            float s2 = __shfl_xor_sync(0xffffffffu, s, o);
            lse_merge(m, s, m2, s2);
        }
        __shared__ float sm[8], ss[8];
        int w = tid >> 5, lane = tid & 31;
        if (lane == 0) { sm[w] = m; ss[w] = s; }
        __syncthreads();
        if (tid == 0) {
            float M = sm[0], S = ss[0];
            for (int i = 1; i < 8; i++) lse_merge(M, S, sm[i], ss[i]);
            slse[0] = M + __logf(S);
        }
    }
}

// phi with obs/init fused
__global__ __launch_bounds__(1024) void phi_k(
    const int* __restrict__ text, const int* __restrict__ w2s,
    const float* __restrict__ trans, const float* __restrict__ tlse,
    const float* __restrict__ L, const float* __restrict__ stlse,
    const float* __restrict__ slog, const float* __restrict__ slse,
    float* __restrict__ phi)
{
    int b = blockIdx.x;
    int n = b / Tm1, t = b % Tm1;
    __shared__ int c0[SPW], c1[SPW];
    __shared__ float ob1[SPW], iob[SPW], tl0[SPW];
    __shared__ float tile[SPW * 33];
    int tid = threadIdx.x;
    if (tid < SPW) {
        int v0 = text[n * Tt + t], v1 = text[n * Tt + t + 1];
        int cc0 = w2s[v0 * SPW + tid], cc1 = w2s[v1 * SPW + tid];
        c0[tid] = cc0; c1[tid] = cc1;
        tl0[tid] = tlse[cc0];
        ob1[tid] = L[v1 * SPW + tid] - stlse[cc1];
        iob[tid] = (t == 0)
            ? (slog[cc0] - slse[0] + L[v0 * SPW + tid] - stlse[cc0]) : 0.f;
    }
    __syncthreads();
    int jw = tid >> 5, kl = tid & 31;
    float val = __ldg(&trans[(size_t)c0[jw] * Cc + c1[kl]]) - tl0[jw] + ob1[kl] + iob[jw];
    tile[jw * 33 + kl] = val;
    __syncthreads();
    int kw = tid >> 5, jl = tid & 31;
    phi[(size_t)(t * Nn + n) * 1024 + kw * SPW + jl] = tile[jl * 33 + kw];
}

// forward / backward scans (bwd: coalesced load + smem transpose)
__global__ __launch_bounds__(1024) void scan_k(
    const float* __restrict__ phi, float* __restrict__ ap, float* __restrict__ bn,
    float* __restrict__ logZ, float* __restrict__ out)
{
    __shared__ float a_s[2][SPW];
    __shared__ float tile[SPW * 33];
    int tid = threadIdx.x, w = tid >> 5, lane = tid & 31;
    bool bwd = blockIdx.x >= Nn;
    int n = bwd ? (int)blockIdx.x - Nn : (int)blockIdx.x;
    if (tid < SPW) a_s[0][tid] = 0.f;
    __syncthreads();
    int cur = 0;
    if (!bwd) {
        float pv = phi[(size_t)n * 1024 + tid];
        for (int t = 0; t < Tm1; t++) {
            float pvn = (t + 1 < Tm1) ? phi[(size_t)((t + 1) * Nn + n) * 1024 + tid] : 0.f;
            if (tid < SPW) ap[(size_t)(t * Nn + n) * SPW + tid] = a_s[cur][tid];
            float x = pv + a_s[cur][lane];
            float m = warp_max(x);
            float s = warp_sum(__expf(x - m));
            if (lane == 0) a_s[cur ^ 1][w] = m + __logf(s);
            __syncthreads();
            cur ^= 1;
            pv = pvn;
        }
        if (w == 0) {
            float x = a_s[cur][lane];
            float m = warp_max(x);
            float s = warp_sum(__expf(x - m));
            float lz = m + __logf(s);
            if (lane == 0) logZ[n] = lz;
            out[2 + n * SPW + lane] = x - lz;
        }
        if (n == 0 && tid == 1023) out[0] = 0.f;
    } else {
        // coalesced load of phi[t][k][j] (tid = k*32+j); transpose via smem
        float pv = phi[(size_t)((Tm1 - 1) * Nn + n) * 1024 + tid];
        for (int t = Tm1 - 1; t >= 0; t--) {
            float pvn = (t > 0) ? phi[(size_t)((t - 1) * Nn + n) * 1024 + tid] : 0.f;
            if (tid < SPW) bn[(size_t)(t * Nn + n) * SPW + tid] = a_s[cur][tid];
            tile[lane * 33 + w] = pv;              // tile[j*33 + k]
            __syncthreads();
            float x = tile[w * 33 + lane] + a_s[cur][lane];  // (j=w, k=lane)
            float m = warp_max(x);
            float s = warp_sum(__expf(x - m));
            if (lane == 0) a_s[cur ^ 1][w] = m + __logf(s);
            __syncthreads();
            cur ^= 1;
            pv = pvn;
        }
    }
}

// elbo + evidence fused
__global__ __launch_bounds__(1024) void elbo_k(
    const float* __restrict__ phi, const float* __restrict__ ap,
    const float* __restrict__ bn, const float* __restrict__ logZ,
    float* __restrict__ out)
{
    int e = blockIdx.x;
    int n = e % Nn;
    __shared__ float sap[SPW], sbn[SPW], ws[32];
    int tid = threadIdx.x;
    if (tid < SPW) { sap[tid] = ap[(size_t)e * SPW + tid]; sbn[tid] = bn[(size_t)e * SPW + tid]; }
    __syncthreads();
    int k = tid >> 5, j = tid & 31;
    float p = phi[(size_t)e * 1024 + tid];
    float term = __expf(sap[j] + p + sbn[k] - logZ[n]) * p;
    term = warp_sum(term);
    if (j == 0) ws[k] = term;
    __syncthreads();
    if (tid < 32) {
        float v = warp_sum(ws[tid]);
        if (tid == 0) atomicAdd(&out[0], v);
    }
    if (e == 0 && tid >= 64 && tid < 96) {
        int lane2 = tid - 64;
        float lz = logZ[lane2];
        lz = warp_sum(lz);
        if (lane2 == 0) out[1] = lz;
    }
}

// ---------------- launcher ----------------
extern "C" void kernel_launch(void* const* d_in, const int* in_sizes, int n_in,
                              void* d_out, int out_size) {
    const float* start_emb = (const float*)d_in[0];
    const float* sw1  = (const float*)d_in[1];
    const float* sb1  = (const float*)d_in[2];
    const float* sw2  = (const float*)d_in[3];
    const float* sb2  = (const float*)d_in[4];
    const float* s_out_w = (const float*)d_in[5];
    const float* s_out_b = (const float*)d_in[6];
    const float* state_emb = (const float*)d_in[7];
    const float* tw1  = (const float*)d_in[8];
    const float* tb1  = (const float*)d_in[9];
    const float* tw2  = (const float*)d_in[10];
    const float* tb2  = (const float*)d_in[11];
    const float* nsp  = (const float*)d_in[12];
    const float* pre_emb = (const float*)d_in[13];
    const float* ew1  = (const float*)d_in[14];
    const float* eb1  = (const float*)d_in[15];
    const float* ew2  = (const float*)d_in[16];
    const float* eb2  = (const float*)d_in[17];
    const float* e_out_w = (const float*)d_in[18];
    const float* e_out_b = (const float*)d_in[19];
    const int* text = (const int*)d_in[20];
    const int* w2s  = (const int*)d_in[21];
    float* out = (float*)d_out;

    float* S = nullptr; int* RM = nullptr; uint32_t* U = nullptr;
    cudaGetSymbolAddress((void**)&S, g_scr);
    cudaGetSymbolAddress((void**)&RM, g_rowmax);
    cudaGetSymbolAddress((void**)&U, g_u);

    static bool inited = false;
    static cudaStream_t s1;
    static cudaEvent_t evStart, evB2, evEm, evP2;
    if (!inited) {
        cudaStreamCreateWithFlags(&s1, cudaStreamNonBlocking);
        cudaEventCreateWithFlags(&evStart, cudaEventDisableTiming);
        cudaEventCreateWithFlags(&evB2, cudaEventDisableTiming);
        cudaEventCreateWithFlags(&evEm, cudaEventDisableTiming);
        cudaEventCreateWithFlags(&evP2, cudaEventDisableTiming);
        cudaFuncSetAttribute(gemm2_h, cudaFuncAttributeMaxDynamicSharedMemorySize, 98304);
        cudaFuncSetAttribute(gemmp_h<1>, cudaFuncAttributeMaxDynamicSharedMemorySize, 73728);
        cudaFuncSetAttribute(gemmp_h<2>, cudaFuncAttributeMaxDynamicSharedMemorySize, 73728);
        inited = true;
    }

    auto HW = [&](int j) { return (__half*)(U + HWB + (size_t)j * 2 * HWS); };
    auto HWl = [&](int j) { return (__half*)(U + HWB + (size_t)j * 2 * HWS + HWS); };
    auto HE = [&](int j) { return (__half*)(U + HEMB + (size_t)j * 2 * HS); };
    auto HEl = [&](int j) { return (__half*)(U + HEMB + (size_t)j * 2 * HS + HS); };
    auto HO = [&](int j) { return (__half*)(U + HOUT + (size_t)j * 2 * HS); };
    auto HOl = [&](int j) { return (__half*)(U + HOUT + (size_t)j * 2 * HS + HS); };

    cudaEventRecord(evStart, 0);
    cudaStreamWaitEvent(s1, evStart, 0);

    // ---- s1: nsp presplit + ewT transpose + inits ----
    prep2_k<<<4288, 256, 0, s1>>>(nsp, (__half*)(U + NSPh), (__half*)(U + NSPl),
                                  e_out_w, S + OFF_EWT, RM, S + OFF_RSUM,
                                  S + OFF_SLOG, s_out_b);
    cudaEventRecord(evP2, s1);

    // ---- main: embeddings presplit + weight splits (MLP inputs only) ----
    Prep P;
    const float* em_[3] = { start_emb, state_emb, pre_emb };
    for (int j = 0; j < 3; j++) {
        P.psrc[j] = em_[j];
        P.phid[j] = HE(j);
        P.plod[j] = HEl(j);
    }
    const float* ws_[6] = { sw1, tw1, ew1, sw2, tw2, ew2 };
    for (int j = 0; j < 6; j++) {
        P.wsrc[j] = ws_[j];
        P.whid[j] = HW(j);
        P.wlod[j] = HWl(j);
    }
    prep_k<<<1152, 256>>>(P);

    // ---- MLPs (fp16 3-split, ldmatrix, 4-stage) ----
    const float* b1_[3] = { sb1, tb1, eb1 };
    PH3 m1;
    for (int j = 0; j < 3; j++)
        m1.p[j] = { HE(j), HEl(j), HW(j), HWl(j), b1_[j], nullptr, nullptr,
                    nullptr, HO(j), HOl(j) };
    gemmp_h<1><<<dim3(4, 32, 3), 256, 73728>>>(m1, nullptr, Hh);

    cudaStreamWaitEvent(0, evP2, 0);   // slog init (MLP2 atomics) + nsp (gemm2)
    PH3 m2;
    m2.p[0] = { HO(0), HOl(0), HW(3), HWl(3), sb2, start_emb, s_out_w,
                nullptr, nullptr, nullptr };
    m2.p[1] = { HO(1), HOl(1), HW(4), HWl(4), tb2, state_emb, nullptr,
                nullptr, (__half*)(U + RSTh), (__half*)(U + RSTl) };
    m2.p[2] = { HO(2), HOl(2), HW(5), HWl(5), eb2, pre_emb, nullptr,
                S + OFF_RP, nullptr, nullptr };
    gemmp_h<2><<<dim3(4, 32, 3), 256, 73728>>>(m2, S + OFF_SLOG, Hh);
    cudaEventRecord(evB2, 0);

    // ---- s1: emission chain (concurrent with trans GEMM) ----
    cudaStreamWaitEvent(s1, evB2, 0);
    emlog_k<<<Vv, 256, 0, s1>>>(S + OFF_RP, S + OFF_EWT, e_out_b, w2s, S + OFF_L, RM);
    emsum_k<<<Vv * SPW / 256, 256, 0, s1>>>(w2s, S + OFF_L, RM, S + OFF_RSUM);
    stlse_k<<<17, 256, 0, s1>>>(RM, S + OFF_RSUM, S + OFF_STLSE, S + OFF_SLOG, S + OFF_SLSE);
    cudaEventRecord(evEm, s1);

    // ---- main: fp16 trans GEMM (4-stage, 2 blocks/SM) + tlse merge ----
    gemm2_h<<<dim3(Cc / 128, Cc / 128), 256, 98304>>>(
        (const __half*)(U + RSTh), (const __half*)(U + RSTl),
        (const __half*)(U + NSPh), (const __half*)(U + NSPl),
        S + OFF_TRANS, (float2*)(S + OFF_PART));
    merge_k<<<512, 256>>>((float2*)(S + OFF_PART), S + OFF_TLSE);

    // ---- join + tail ----
    cudaStreamWaitEvent(0, evEm, 0);
    phi_k<<<Nn * Tm1, 1024>>>(text, w2s, S + OFF_TRANS, S + OFF_TLSE,
                              S + OFF_L, S + OFF_STLSE, S + OFF_SLOG, S + OFF_SLSE,
                              S + OFF_PHI);
    scan_k<<<2 * Nn, 1024>>>(S + OFF_PHI, S + OFF_AP, S + OFF_BN, S + OFF_LOGZ, out);
    elbo_k<<<Tm1 * Nn, 1024>>>(S + OFF_PHI, S + OFF_AP, S + OFF_BN, S + OFF_LOGZ, out);
}